// round 2
// baseline (speedup 1.0000x reference)
#include <cuda_runtime.h>
#include <cstdint>

#define NN   100000
#define EE   1600000
#define FIN  128
#define HH   128
#define OUTC 64

// ---------------- scratch (no allocation allowed) ----------------
__device__ __align__(16) float g_dinv[NN];
__device__ __align__(16) float g_norm[EE];
__device__ __align__(16) float g_t  [(size_t)NN * HH];   // GEMM output
__device__ __align__(16) float g_agg[(size_t)NN * HH];   // aggregation accumulator
__device__ __align__(16) float g_h  [(size_t)NN * HH];   // layer activation

// ---------------- vector reductions ----------------
__device__ __forceinline__ void red_add_v4(float* p, float4 v) {
    asm volatile("red.global.add.v4.f32 [%0], {%1,%2,%3,%4};"
                 :: "l"(p), "f"(v.x), "f"(v.y), "f"(v.z), "f"(v.w) : "memory");
}
__device__ __forceinline__ void red_add_v2(float* p, float2 v) {
    asm volatile("red.global.add.v2.f32 [%0], {%1,%2};"
                 :: "l"(p), "f"(v.x), "f"(v.y) : "memory");
}

// ---------------- degree / norm ----------------
__global__ void k_deg_init(int n) {
    int i = blockIdx.x * blockDim.x + threadIdx.x;
    if (i < n) g_dinv[i] = 1.0f;   // self-loop contributes 1 to every node's degree
}
__global__ void k_deg_acc(const int* __restrict__ dst, int e) {
    int i = blockIdx.x * blockDim.x + threadIdx.x;
    if (i < e) atomicAdd(&g_dinv[dst[i]], 1.0f);
}
__global__ void k_rsqrt(int n) {
    int i = blockIdx.x * blockDim.x + threadIdx.x;
    if (i < n) g_dinv[i] = rsqrtf(g_dinv[i]);   // deg >= 1 always
}
__global__ void k_norm(const int* __restrict__ src,
                       const int* __restrict__ dst, int e) {
    int i = blockIdx.x * blockDim.x + threadIdx.x;
    if (i < e) g_norm[i] = g_dinv[src[i]] * g_dinv[dst[i]];
}

// ---------------- GEMM: out[M,DOUT] = A[M,128] @ W[128,DOUT] ----------------
// 256 threads, 64 rows/block. Whole W + 64x128 A tile staged in SMEM (dynamic).
template<int DOUT>
__global__ void k_gemm(const float* __restrict__ Ax, const float* __restrict__ W,
                       int M, int from_h) {
    constexpr int DIN = 128;
    constexpr int AST = DIN + 4;           // padded A stride (avoid bank conflicts)
    extern __shared__ float sm[];
    float* Ws = sm;                        // DIN*DOUT
    float* As = sm + DIN * DOUT;           // 64*AST

    const float* A = from_h ? g_h : Ax;
    int tid  = threadIdx.x;
    int row0 = blockIdx.x * 64;

    for (int i = tid; i < DIN * DOUT / 4; i += 256)
        ((float4*)Ws)[i] = ((const float4*)W)[i];

    for (int i = tid; i < 64 * (DIN / 4); i += 256) {
        int r  = i >> 5;                   // DIN/4 == 32
        int c4 = i & 31;
        int gr = row0 + r;
        float4 v = make_float4(0.f, 0.f, 0.f, 0.f);
        if (gr < M) v = ((const float4*)A)[(size_t)gr * 32 + c4];
        *(float4*)(As + r * AST + c4 * 4) = v;
    }
    __syncthreads();

    constexpr int TC = DOUT / 16;          // cols per thread (8 or 4)
    int r0 = (tid >> 4) * 4;
    int c0 = (tid & 15) * TC;

    float acc[4][TC];
#pragma unroll
    for (int i = 0; i < 4; i++)
#pragma unroll
        for (int c = 0; c < TC; c++) acc[i][c] = 0.f;

#pragma unroll 8
    for (int k = 0; k < DIN; k++) {
        float a[4];
#pragma unroll
        for (int i = 0; i < 4; i++) a[i] = As[(r0 + i) * AST + k];
        float b[TC];
#pragma unroll
        for (int c = 0; c < TC; c++) b[c] = Ws[k * DOUT + c0 + c];
#pragma unroll
        for (int i = 0; i < 4; i++)
#pragma unroll
            for (int c = 0; c < TC; c++)
                acc[i][c] = fmaf(a[i], b[c], acc[i][c]);
    }

#pragma unroll
    for (int i = 0; i < 4; i++) {
        int gr = row0 + r0 + i;
        if (gr < M) {
#pragma unroll
            for (int c = 0; c < TC; c += 4)
                *(float4*)&g_t[(size_t)gr * DOUT + c0 + c] =
                    make_float4(acc[i][c], acc[i][c+1], acc[i][c+2], acc[i][c+3]);
        }
    }
}

// ---------------- self-loop message = dinv[i]^2 * t[i]  (also inits agg) ----------------
template<int DOUT>
__global__ void k_selfinit(int n) {
    int idx = blockIdx.x * blockDim.x + threadIdx.x;
    int tot = n * (DOUT / 4);
    if (idx >= tot) return;
    int row = idx / (DOUT / 4);
    float s = g_dinv[row]; s *= s;
    float4 v = ((const float4*)g_t)[idx];
    v.x *= s; v.y *= s; v.z *= s; v.w *= s;
    ((float4*)g_agg)[idx] = v;
}

// ---------------- warp-per-edge scatter: agg[dst] += norm * t[src] ----------------
__global__ void k_scatter128(const int* __restrict__ srcp,
                             const int* __restrict__ dstp, int e) {
    int gw   = (blockIdx.x * blockDim.x + threadIdx.x) >> 5;
    int lane = threadIdx.x & 31;
    if (gw >= e) return;
    int s = __ldg(&srcp[gw]);
    int d = __ldg(&dstp[gw]);
    float nrm = g_norm[gw];
    float4 v = ((const float4*)g_t)[(size_t)s * 32 + lane];
    v.x *= nrm; v.y *= nrm; v.z *= nrm; v.w *= nrm;
    red_add_v4(&g_agg[(size_t)d * 128 + lane * 4], v);
}
__global__ void k_scatter64(const int* __restrict__ srcp,
                            const int* __restrict__ dstp, int e) {
    int gw   = (blockIdx.x * blockDim.x + threadIdx.x) >> 5;
    int lane = threadIdx.x & 31;
    if (gw >= e) return;
    int s = __ldg(&srcp[gw]);
    int d = __ldg(&dstp[gw]);
    float nrm = g_norm[gw];
    float2 v = ((const float2*)g_t)[(size_t)s * 32 + lane];
    v.x *= nrm; v.y *= nrm;
    red_add_v2(&g_agg[(size_t)d * 64 + lane * 2], v);
}

// ---------------- bias + relu -> g_h ----------------
template<int DOUT>
__global__ void k_bias_relu(const float* __restrict__ b, int n) {
    int idx = blockIdx.x * blockDim.x + threadIdx.x;
    int tot = n * (DOUT / 4);
    if (idx >= tot) return;
    int c4 = idx % (DOUT / 4);
    float4 v  = ((const float4*)g_agg)[idx];
    float4 bb = ((const float4*)b)[c4];
    v.x = fmaxf(v.x + bb.x, 0.f);
    v.y = fmaxf(v.y + bb.y, 0.f);
    v.z = fmaxf(v.z + bb.z, 0.f);
    v.w = fmaxf(v.w + bb.w, 0.f);
    ((float4*)g_h)[idx] = v;
}

// ---------------- bias + log_softmax (warp per node, 64 cols) ----------------
__global__ void k_logsoftmax(const float* __restrict__ b3, float* __restrict__ out, int n) {
    int w    = (blockIdx.x * blockDim.x + threadIdx.x) >> 5;
    int lane = threadIdx.x & 31;
    if (w >= n) return;
    float2 v  = *(const float2*)&g_agg[(size_t)w * 64 + lane * 2];
    float2 bb = *(const float2*)&b3[lane * 2];
    v.x += bb.x; v.y += bb.y;
    float m = fmaxf(v.x, v.y);
#pragma unroll
    for (int o = 16; o; o >>= 1) m = fmaxf(m, __shfl_xor_sync(0xffffffffu, m, o));
    float sum = expf(v.x - m) + expf(v.y - m);
#pragma unroll
    for (int o = 16; o; o >>= 1) sum += __shfl_xor_sync(0xffffffffu, sum, o);
    float lse = m + logf(sum);
    *(float2*)&out[(size_t)w * 64 + lane * 2] = make_float2(v.x - lse, v.y - lse);
}

// ---------------- launch ----------------
extern "C" void kernel_launch(void* const* d_in, const int* in_sizes, int n_in,
                              void* d_out, int out_size) {
    const float* x   = (const float*)d_in[0];
    const int*   ei  = (const int*)d_in[1];     // JAX x64 disabled -> int32
    const float* W1  = (const float*)d_in[2];
    const float* b1  = (const float*)d_in[3];
    const float* W2  = (const float*)d_in[4];
    const float* b2  = (const float*)d_in[5];
    const float* W3  = (const float*)d_in[6];
    const float* b3  = (const float*)d_in[7];
    float* out = (float*)d_out;

    int n = in_sizes[0] / FIN;
    int e = in_sizes[1] / 2;
    const int* srcp = ei;
    const int* dstp = ei + e;

    const int smem128 = (FIN * HH   + 64 * (FIN + 4)) * sizeof(float); // ~97 KB
    const int smem64  = (FIN * OUTC + 64 * (FIN + 4)) * sizeof(float); // ~65 KB
    cudaFuncSetAttribute(k_gemm<HH>,   cudaFuncAttributeMaxDynamicSharedMemorySize, smem128);
    cudaFuncSetAttribute(k_gemm<OUTC>, cudaFuncAttributeMaxDynamicSharedMemorySize, smem64);

    int gb;

    // degrees + norms
    gb = (n + 255) / 256;  k_deg_init<<<gb, 256>>>(n);
    gb = (e + 255) / 256;  k_deg_acc<<<gb, 256>>>(dstp, e);
    gb = (n + 255) / 256;  k_rsqrt<<<gb, 256>>>(n);
    gb = (e + 255) / 256;  k_norm<<<gb, 256>>>(srcp, dstp, e);

    int gemm_blocks = (n + 63) / 64;
    int ew_blocks128 = (n * (HH / 4)   + 255) / 256;
    int ew_blocks64  = (n * (OUTC / 4) + 255) / 256;
    int scat_blocks  = (int)(((long long)e * 32 + 255) / 256);

    // layer 1: x @ W1 -> aggregate -> relu(+b1)
    k_gemm<HH><<<gemm_blocks, 256, smem128>>>(x, W1, n, 0);
    k_selfinit<HH><<<ew_blocks128, 256>>>(n);
    k_scatter128<<<scat_blocks, 256>>>(srcp, dstp, e);
    k_bias_relu<HH><<<ew_blocks128, 256>>>(b1, n);

    // layer 2: h @ W2 -> aggregate -> relu(+b2)
    k_gemm<HH><<<gemm_blocks, 256, smem128>>>(x, W2, n, 1);
    k_selfinit<HH><<<ew_blocks128, 256>>>(n);
    k_scatter128<<<scat_blocks, 256>>>(srcp, dstp, e);
    k_bias_relu<HH><<<ew_blocks128, 256>>>(b2, n);

    // layer 3: h @ W3 -> aggregate -> +b3, log_softmax
    k_gemm<OUTC><<<gemm_blocks, 256, smem64>>>(x, W3, n, 1);
    k_selfinit<OUTC><<<ew_blocks64, 256>>>(n);
    k_scatter64<<<scat_blocks, 256>>>(srcp, dstp, e);
    k_logsoftmax<<<(n * 32 + 255) / 256, 256>>>(b3, out, n);
}

// round 3
// speedup vs baseline: 1.6887x; 1.6887x over previous
#include <cuda_runtime.h>
#include <cstdint>

#define NN   100000
#define EE   1600000
#define FIN  128
#define HH   128
#define OUTC 64

// ---------------- scratch (no allocation allowed) ----------------
__device__ __align__(16) int   g_cnt[NN];
__device__ __align__(16) int   g_rowptr[NN + 1];
__device__ __align__(16) int   g_cursor[NN];
__device__ __align__(16) int   g_bsum[256];
__device__ __align__(16) float g_dinv[NN];
__device__ __align__(16) int   g_csr_src[EE];
__device__ __align__(16) float g_t[(size_t)NN * HH];   // GEMM output (pre-scaled by dinv)
__device__ __align__(16) float g_h[(size_t)NN * HH];   // layer activation

// ================= CSR construction =================
__global__ void k_zero(int n) {
    int i = blockIdx.x * blockDim.x + threadIdx.x;
    if (i < n) g_cnt[i] = 0;
}
__global__ void k_count(const int* __restrict__ dst, int e) {
    int i = blockIdx.x * blockDim.x + threadIdx.x;
    if (i < e) atomicAdd(&g_cnt[dst[i]], 1);
}
// per-block exclusive scan (1024 elems/block)
__global__ void k_scan1(int n) {
    __shared__ int sh[1024];
    int tid = threadIdx.x;
    int i = blockIdx.x * 1024 + tid;
    int v = (i < n) ? g_cnt[i] : 0;
    sh[tid] = v;
    __syncthreads();
#pragma unroll
    for (int off = 1; off < 1024; off <<= 1) {
        int t = (tid >= off) ? sh[tid - off] : 0;
        __syncthreads();
        sh[tid] += t;
        __syncthreads();
    }
    if (i < n) g_rowptr[i] = sh[tid] - v;       // exclusive
    if (tid == 1023) g_bsum[blockIdx.x] = sh[1023];
}
__global__ void k_scan2(int nb, int n) {
    int s = 0;
    for (int b = 0; b < nb; b++) { int t = g_bsum[b]; g_bsum[b] = s; s += t; }
    g_rowptr[n] = s;
}
__global__ void k_scan3(int n) {   // add block offsets, init cursor, compute dinv
    int i = blockIdx.x * blockDim.x + threadIdx.x;
    if (i >= n) return;
    int v = g_rowptr[i] + g_bsum[i >> 10];
    g_rowptr[i] = v;
    g_cursor[i] = v;
    g_dinv[i] = rsqrtf(1.0f + (float)g_cnt[i]);   // +1 for self-loop
}
__global__ void k_fill(const int* __restrict__ src, const int* __restrict__ dst, int e) {
    int i = blockIdx.x * blockDim.x + threadIdx.x;
    if (i >= e) return;
    int d = dst[i];
    int pos = atomicAdd(&g_cursor[d], 1);
    g_csr_src[pos] = src[i];
}

// ================= GEMM: g_t[M,DOUT] = dinv[row] * (A[M,128] @ W[128,DOUT]) =================
// 256 threads, 64 rows per block. W + A tile in SMEM. k-chunked float4 inner loop.
template<int DOUT>
__global__ void k_gemm(const float* __restrict__ Ax, const float* __restrict__ W,
                       int M, int from_h) {
    constexpr int DIN = 128;
    constexpr int AST = DIN + 4;           // padded stride, multiple of 4 (float4 ok)
    extern __shared__ float sm[];
    float* Ws = sm;                        // DIN*DOUT
    float* As = sm + DIN * DOUT;           // 64*AST

    const float* A = from_h ? g_h : Ax;
    int tid  = threadIdx.x;
    int row0 = blockIdx.x * 64;

    for (int i = tid; i < DIN * DOUT / 4; i += 256)
        ((float4*)Ws)[i] = ((const float4*)W)[i];

    for (int i = tid; i < 64 * (DIN / 4); i += 256) {
        int r  = i >> 5;
        int c4 = i & 31;
        int gr = row0 + r;
        float4 v = make_float4(0.f, 0.f, 0.f, 0.f);
        if (gr < M) v = ((const float4*)A)[(size_t)gr * 32 + c4];
        *(float4*)(As + r * AST + c4 * 4) = v;
    }
    __syncthreads();

    constexpr int TC = DOUT / 16;          // 8 or 4 cols/thread
    int r0 = (tid >> 4) * 4;
    int c0 = (tid & 15) * TC;

    float acc[4][TC];
#pragma unroll
    for (int i = 0; i < 4; i++)
#pragma unroll
        for (int c = 0; c < TC; c++) acc[i][c] = 0.f;

#pragma unroll 2
    for (int kk = 0; kk < DIN; kk += 4) {
        float av[4][4];
#pragma unroll
        for (int i = 0; i < 4; i++)
            *(float4*)av[i] = *(const float4*)&As[(r0 + i) * AST + kk];
#pragma unroll
        for (int j = 0; j < 4; j++) {
            float b[TC];
#pragma unroll
            for (int c = 0; c < TC; c += 4)
                *(float4*)&b[c] = *(const float4*)&Ws[(kk + j) * DOUT + c0 + c];
#pragma unroll
            for (int i = 0; i < 4; i++)
#pragma unroll
                for (int c = 0; c < TC; c++)
                    acc[i][c] = fmaf(av[i][j], b[c], acc[i][c]);
        }
    }

#pragma unroll
    for (int i = 0; i < 4; i++) {
        int gr = row0 + r0 + i;
        if (gr < M) {
            float s = g_dinv[gr];
#pragma unroll
            for (int c = 0; c < TC; c += 4)
                *(float4*)&g_t[(size_t)gr * DOUT + c0 + c] =
                    make_float4(s * acc[i][c], s * acc[i][c+1],
                                s * acc[i][c+2], s * acc[i][c+3]);
        }
    }
}

// ================= Aggregation (warp per node), fused epilogue =================
// acc = t[i] + sum_{s in N(i)} t[s];  res = dinv[i]*acc + bias
// MODE 0: relu -> g_h      MODE 1: log_softmax -> out (DOUT=64)
template<int DOUT, int MODE>
__global__ void k_agg(const float* __restrict__ bias, float* __restrict__ out, int n) {
    int w    = (blockIdx.x * blockDim.x + threadIdx.x) >> 5;
    int lane = threadIdx.x & 31;
    if (w >= n) return;
    constexpr int VF = DOUT / 32;          // 4 or 2 floats per lane

    float acc[VF];
    {   // self term
        const float* p = g_t + (size_t)w * DOUT + lane * VF;
        if (VF == 4) { float4 v = *(const float4*)p; acc[0]=v.x; acc[1]=v.y; acc[2]=v.z; acc[3]=v.w; }
        else         { float2 v = *(const float2*)p; acc[0]=v.x; acc[1]=v.y; }
    }

    int beg = g_rowptr[w], end = g_rowptr[w + 1];
    for (int jb = beg; jb < end; jb += 32) {
        int myj = jb + lane;
        int ms  = (myj < end) ? g_csr_src[myj] : 0;
        int cnt = min(32, end - jb);
        int k = 0;
        for (; k + 4 <= cnt; k += 4) {
            int s0 = __shfl_sync(0xffffffffu, ms, k);
            int s1 = __shfl_sync(0xffffffffu, ms, k + 1);
            int s2 = __shfl_sync(0xffffffffu, ms, k + 2);
            int s3 = __shfl_sync(0xffffffffu, ms, k + 3);
            if (VF == 4) {
                float4 v0 = *(const float4*)(g_t + (size_t)s0 * DOUT + lane * 4);
                float4 v1 = *(const float4*)(g_t + (size_t)s1 * DOUT + lane * 4);
                float4 v2 = *(const float4*)(g_t + (size_t)s2 * DOUT + lane * 4);
                float4 v3 = *(const float4*)(g_t + (size_t)s3 * DOUT + lane * 4);
                acc[0] += (v0.x + v1.x) + (v2.x + v3.x);
                acc[1] += (v0.y + v1.y) + (v2.y + v3.y);
                acc[2] += (v0.z + v1.z) + (v2.z + v3.z);
                acc[3] += (v0.w + v1.w) + (v2.w + v3.w);
            } else {
                float2 v0 = *(const float2*)(g_t + (size_t)s0 * DOUT + lane * 2);
                float2 v1 = *(const float2*)(g_t + (size_t)s1 * DOUT + lane * 2);
                float2 v2 = *(const float2*)(g_t + (size_t)s2 * DOUT + lane * 2);
                float2 v3 = *(const float2*)(g_t + (size_t)s3 * DOUT + lane * 2);
                acc[0] += (v0.x + v1.x) + (v2.x + v3.x);
                acc[1] += (v0.y + v1.y) + (v2.y + v3.y);
            }
        }
        for (; k < cnt; k++) {
            int s = __shfl_sync(0xffffffffu, ms, k);
            if (VF == 4) {
                float4 v = *(const float4*)(g_t + (size_t)s * DOUT + lane * 4);
                acc[0] += v.x; acc[1] += v.y; acc[2] += v.z; acc[3] += v.w;
            } else {
                float2 v = *(const float2*)(g_t + (size_t)s * DOUT + lane * 2);
                acc[0] += v.x; acc[1] += v.y;
            }
        }
    }

    float di = g_dinv[w];
    if (MODE == 0) {   // bias + relu -> g_h
        float4 bb = ((const float4*)bias)[lane];
        float4 r;
        r.x = fmaxf(fmaf(di, acc[0], bb.x), 0.f);
        r.y = fmaxf(fmaf(di, acc[1], bb.y), 0.f);
        r.z = fmaxf(fmaf(di, acc[2], bb.z), 0.f);
        r.w = fmaxf(fmaf(di, acc[3], bb.w), 0.f);
        *(float4*)(g_h + (size_t)w * DOUT + lane * 4) = r;
    } else {           // bias + log_softmax -> out (64 cols)
        float2 bb = ((const float2*)bias)[lane];
        float vx = fmaf(di, acc[0], bb.x);
        float vy = fmaf(di, acc[1], bb.y);
        float m = fmaxf(vx, vy);
#pragma unroll
        for (int o = 16; o; o >>= 1) m = fmaxf(m, __shfl_xor_sync(0xffffffffu, m, o));
        float sum = expf(vx - m) + expf(vy - m);
#pragma unroll
        for (int o = 16; o; o >>= 1) sum += __shfl_xor_sync(0xffffffffu, sum, o);
        float lse = m + logf(sum);
        *(float2*)(out + (size_t)w * 64 + lane * 2) = make_float2(vx - lse, vy - lse);
    }
}

// ================= launch =================
extern "C" void kernel_launch(void* const* d_in, const int* in_sizes, int n_in,
                              void* d_out, int out_size) {
    const float* x   = (const float*)d_in[0];
    const int*   ei  = (const int*)d_in[1];     // int32 (JAX x64 disabled)
    const float* W1  = (const float*)d_in[2];
    const float* b1  = (const float*)d_in[3];
    const float* W2  = (const float*)d_in[4];
    const float* b2  = (const float*)d_in[5];
    const float* W3  = (const float*)d_in[6];
    const float* b3  = (const float*)d_in[7];
    float* out = (float*)d_out;

    int n = in_sizes[0] / FIN;
    int e = in_sizes[1] / 2;
    const int* srcp = ei;
    const int* dstp = ei + e;

    const int smem128 = (FIN * HH   + 64 * (FIN + 4)) * sizeof(float);
    const int smem64  = (FIN * OUTC + 64 * (FIN + 4)) * sizeof(float);
    cudaFuncSetAttribute(k_gemm<HH>,   cudaFuncAttributeMaxDynamicSharedMemorySize, smem128);
    cudaFuncSetAttribute(k_gemm<OUTC>, cudaFuncAttributeMaxDynamicSharedMemorySize, smem64);

    int nb_scan = (n + 1023) >> 10;

    // ---- CSR build + dinv ----
    k_zero <<<(n + 255) / 256, 256>>>(n);
    k_count<<<(e + 255) / 256, 256>>>(dstp, e);
    k_scan1<<<nb_scan, 1024>>>(n);
    k_scan2<<<1, 1>>>(nb_scan, n);
    k_scan3<<<(n + 255) / 256, 256>>>(n);
    k_fill <<<(e + 255) / 256, 256>>>(srcp, dstp, e);

    int gemm_blocks = (n + 63) / 64;
    int agg_blocks  = (int)(((long long)n * 32 + 255) / 256);

    // ---- layer 1 ----
    k_gemm<HH><<<gemm_blocks, 256, smem128>>>(x, W1, n, 0);
    k_agg<HH, 0><<<agg_blocks, 256>>>(b1, nullptr, n);
    // ---- layer 2 ----
    k_gemm<HH><<<gemm_blocks, 256, smem128>>>(x, W2, n, 1);
    k_agg<HH, 0><<<agg_blocks, 256>>>(b2, nullptr, n);
    // ---- layer 3 ----
    k_gemm<OUTC><<<gemm_blocks, 256, smem64>>>(x, W3, n, 1);
    k_agg<OUTC, 1><<<agg_blocks, 256>>>(b3, out, n);
}

// round 4
// speedup vs baseline: 1.7296x; 1.0243x over previous
#include <cuda_runtime.h>
#include <cstdint>

#define NN   100000
#define EE   1600000
#define FIN  128
#define HH   128
#define OUTC 64

// ---------------- scratch (no allocation allowed) ----------------
__device__ __align__(16) int   g_cnt[NN];
__device__ __align__(16) int   g_rowptr[NN + 1];
__device__ __align__(16) int   g_cursor[NN];
__device__ __align__(16) int   g_bsum[256];
__device__ __align__(16) float g_dinv[NN];
__device__ __align__(16) int   g_csr_src[EE];
__device__ __align__(16) float g_t[(size_t)NN * HH];   // GEMM output (pre-scaled by dinv)
__device__ __align__(16) float g_h[(size_t)NN * HH];   // layer activation

// ================= CSR construction =================
__global__ void k_zero(int n) {
    int i = blockIdx.x * blockDim.x + threadIdx.x;
    if (i < n) g_cnt[i] = 0;
}
__global__ void k_count(const int* __restrict__ dst, int e) {
    int i = blockIdx.x * blockDim.x + threadIdx.x;
    if (i < e) atomicAdd(&g_cnt[dst[i]], 1);
}
// per-block exclusive scan (1024 elems/block) + dinv (needs only cnt)
__global__ void k_scan1(int n) {
    __shared__ int sh[1024];
    int tid = threadIdx.x;
    int i = blockIdx.x * 1024 + tid;
    int v = (i < n) ? g_cnt[i] : 0;
    sh[tid] = v;
    __syncthreads();
#pragma unroll
    for (int off = 1; off < 1024; off <<= 1) {
        int t = (tid >= off) ? sh[tid - off] : 0;
        __syncthreads();
        sh[tid] += t;
        __syncthreads();
    }
    if (i < n) {
        g_rowptr[i] = sh[tid] - v;                 // exclusive, local
        g_dinv[i]   = rsqrtf(1.0f + (float)v);     // +1 self-loop
    }
    if (tid == 1023) g_bsum[blockIdx.x] = sh[1023];
}
// parallel scan of block sums (nb <= 128), one 128-thread block
__global__ void k_scan2(int nb, int n) {
    __shared__ int sh[128];
    int tid = threadIdx.x;
    int v = (tid < nb) ? g_bsum[tid] : 0;
    sh[tid] = v;
    __syncthreads();
#pragma unroll
    for (int off = 1; off < 128; off <<= 1) {
        int t = (tid >= off) ? sh[tid - off] : 0;
        __syncthreads();
        sh[tid] += t;
        __syncthreads();
    }
    if (tid < nb) g_bsum[tid] = sh[tid] - v;   // exclusive
    if (tid == 127) g_rowptr[n] = sh[127];     // total
}
__global__ void k_scan3(int n) {   // add block offsets, init cursor
    int i = blockIdx.x * blockDim.x + threadIdx.x;
    if (i >= n) return;
    int v = g_rowptr[i] + g_bsum[i >> 10];
    g_rowptr[i] = v;
    g_cursor[i] = v;
}
__global__ void k_fill(const int* __restrict__ src, const int* __restrict__ dst, int e) {
    int i = blockIdx.x * blockDim.x + threadIdx.x;
    if (i >= e) return;
    int d = dst[i];
    int pos = atomicAdd(&g_cursor[d], 1);
    g_csr_src[pos] = src[i];
}

// ================= GEMM: g_t[M,DOUT] = dinv[row] * (A[M,128] @ W[128,DOUT]) =================
// 256 threads, 128-row tile, 8x(DOUT/16) per-thread register block. W + A fully in SMEM.
template<int DOUT>
__global__ __launch_bounds__(256, 1)
void k_gemm(const float* __restrict__ Ax, const float* __restrict__ W,
            int M, int from_h) {
    constexpr int DIN = 128;
    constexpr int AST = DIN + 4;           // padded stride (multiple of 4 -> float4 ok)
    extern __shared__ float sm[];
    float* Ws = sm;                        // DIN*DOUT
    float* As = sm + DIN * DOUT;           // 128*AST

    const float* A = from_h ? g_h : Ax;
    int tid  = threadIdx.x;
    int row0 = blockIdx.x * 128;

    for (int i = tid; i < DIN * DOUT / 4; i += 256)
        ((float4*)Ws)[i] = ((const float4*)W)[i];

    for (int i = tid; i < 128 * 32; i += 256) {
        int r  = i >> 5;
        int c4 = i & 31;
        int gr = row0 + r;
        float4 v = make_float4(0.f, 0.f, 0.f, 0.f);
        if (gr < M) v = ((const float4*)A)[(size_t)gr * 32 + c4];
        *(float4*)(As + r * AST + c4 * 4) = v;
    }
    __syncthreads();

    constexpr int TC = DOUT / 16;          // 8 or 4 cols/thread
    int r0 = (tid >> 4) * 8;
    int c0 = (tid & 15) * TC;

    float acc[8][TC];
#pragma unroll
    for (int i = 0; i < 8; i++)
#pragma unroll
        for (int c = 0; c < TC; c++) acc[i][c] = 0.f;

    for (int kk = 0; kk < DIN; kk += 4) {
        float4 av[8];
#pragma unroll
        for (int i = 0; i < 8; i++)
            av[i] = *(const float4*)&As[(r0 + i) * AST + kk];
#pragma unroll
        for (int j = 0; j < 4; j++) {
            float b[TC];
#pragma unroll
            for (int c = 0; c < TC; c += 4)
                *(float4*)&b[c] = *(const float4*)&Ws[(kk + j) * DOUT + c0 + c];
#pragma unroll
            for (int i = 0; i < 8; i++) {
                float a = (j == 0) ? av[i].x : (j == 1) ? av[i].y
                        : (j == 2) ? av[i].z : av[i].w;
#pragma unroll
                for (int c = 0; c < TC; c++)
                    acc[i][c] = fmaf(a, b[c], acc[i][c]);
            }
        }
    }

#pragma unroll
    for (int i = 0; i < 8; i++) {
        int gr = row0 + r0 + i;
        if (gr < M) {
            float s = g_dinv[gr];
#pragma unroll
            for (int c = 0; c < TC; c += 4)
                *(float4*)&g_t[(size_t)gr * DOUT + c0 + c] =
                    make_float4(s * acc[i][c], s * acc[i][c+1],
                                s * acc[i][c+2], s * acc[i][c+3]);
        }
    }
}

// ================= Aggregation (warp per node), fused epilogue =================
// acc = t[i] + sum_{s in N(i)} t[s];  res = dinv[i]*acc + bias
// MODE 0: relu -> g_h      MODE 1: log_softmax -> out (DOUT=64)
template<int DOUT, int MODE>
__global__ void k_agg(const float* __restrict__ bias, float* __restrict__ out, int n) {
    int w    = (blockIdx.x * blockDim.x + threadIdx.x) >> 5;
    int lane = threadIdx.x & 31;
    if (w >= n) return;
    constexpr int VF = DOUT / 32;          // 4 or 2 floats per lane

    float acc[VF];
    {   // self term
        const float* p = g_t + (size_t)w * DOUT + lane * VF;
        if (VF == 4) { float4 v = *(const float4*)p; acc[0]=v.x; acc[1]=v.y; acc[2]=v.z; acc[3]=v.w; }
        else         { float2 v = *(const float2*)p; acc[0]=v.x; acc[1]=v.y; }
    }

    int beg = g_rowptr[w], end = g_rowptr[w + 1];
    for (int jb = beg; jb < end; jb += 32) {
        int myj = jb + lane;
        int ms  = (myj < end) ? g_csr_src[myj] : 0;
        int cnt = min(32, end - jb);
        int k = 0;
        for (; k + 4 <= cnt; k += 4) {
            int s0 = __shfl_sync(0xffffffffu, ms, k);
            int s1 = __shfl_sync(0xffffffffu, ms, k + 1);
            int s2 = __shfl_sync(0xffffffffu, ms, k + 2);
            int s3 = __shfl_sync(0xffffffffu, ms, k + 3);
            if (VF == 4) {
                float4 v0 = *(const float4*)(g_t + (size_t)s0 * DOUT + lane * 4);
                float4 v1 = *(const float4*)(g_t + (size_t)s1 * DOUT + lane * 4);
                float4 v2 = *(const float4*)(g_t + (size_t)s2 * DOUT + lane * 4);
                float4 v3 = *(const float4*)(g_t + (size_t)s3 * DOUT + lane * 4);
                acc[0] += (v0.x + v1.x) + (v2.x + v3.x);
                acc[1] += (v0.y + v1.y) + (v2.y + v3.y);
                acc[2] += (v0.z + v1.z) + (v2.z + v3.z);
                acc[3] += (v0.w + v1.w) + (v2.w + v3.w);
            } else {
                float2 v0 = *(const float2*)(g_t + (size_t)s0 * DOUT + lane * 2);
                float2 v1 = *(const float2*)(g_t + (size_t)s1 * DOUT + lane * 2);
                float2 v2 = *(const float2*)(g_t + (size_t)s2 * DOUT + lane * 2);
                float2 v3 = *(const float2*)(g_t + (size_t)s3 * DOUT + lane * 2);
                acc[0] += (v0.x + v1.x) + (v2.x + v3.x);
                acc[1] += (v0.y + v1.y) + (v2.y + v3.y);
            }
        }
        for (; k < cnt; k++) {
            int s = __shfl_sync(0xffffffffu, ms, k);
            if (VF == 4) {
                float4 v = *(const float4*)(g_t + (size_t)s * DOUT + lane * 4);
                acc[0] += v.x; acc[1] += v.y; acc[2] += v.z; acc[3] += v.w;
            } else {
                float2 v = *(const float2*)(g_t + (size_t)s * DOUT + lane * 2);
                acc[0] += v.x; acc[1] += v.y;
            }
        }
    }

    float di = g_dinv[w];
    if (MODE == 0) {   // bias + relu -> g_h
        float4 bb = ((const float4*)bias)[lane];
        float4 r;
        r.x = fmaxf(fmaf(di, acc[0], bb.x), 0.f);
        r.y = fmaxf(fmaf(di, acc[1], bb.y), 0.f);
        r.z = fmaxf(fmaf(di, acc[2], bb.z), 0.f);
        r.w = fmaxf(fmaf(di, acc[3], bb.w), 0.f);
        *(float4*)(g_h + (size_t)w * DOUT + lane * 4) = r;
    } else {           // bias + log_softmax -> out (64 cols)
        float2 bb = ((const float2*)bias)[lane];
        float vx = fmaf(di, acc[0], bb.x);
        float vy = fmaf(di, acc[1], bb.y);
        float m = fmaxf(vx, vy);
#pragma unroll
        for (int o = 16; o; o >>= 1) m = fmaxf(m, __shfl_xor_sync(0xffffffffu, m, o));
        float sum = expf(vx - m) + expf(vy - m);
#pragma unroll
        for (int o = 16; o; o >>= 1) sum += __shfl_xor_sync(0xffffffffu, sum, o);
        float lse = m + logf(sum);
        *(float2*)(out + (size_t)w * 64 + lane * 2) = make_float2(vx - lse, vy - lse);
    }
}

// ================= launch =================
extern "C" void kernel_launch(void* const* d_in, const int* in_sizes, int n_in,
                              void* d_out, int out_size) {
    const float* x   = (const float*)d_in[0];
    const int*   ei  = (const int*)d_in[1];     // int32 (JAX x64 disabled)
    const float* W1  = (const float*)d_in[2];
    const float* b1  = (const float*)d_in[3];
    const float* W2  = (const float*)d_in[4];
    const float* b2  = (const float*)d_in[5];
    const float* W3  = (const float*)d_in[6];
    const float* b3  = (const float*)d_in[7];
    float* out = (float*)d_out;

    int n = in_sizes[0] / FIN;
    int e = in_sizes[1] / 2;
    const int* srcp = ei;
    const int* dstp = ei + e;

    const int smem128 = (FIN * HH   + 128 * (FIN + 4)) * sizeof(float); // ~130 KB
    const int smem64  = (FIN * OUTC + 128 * (FIN + 4)) * sizeof(float); // ~98 KB
    cudaFuncSetAttribute(k_gemm<HH>,   cudaFuncAttributeMaxDynamicSharedMemorySize, smem128);
    cudaFuncSetAttribute(k_gemm<OUTC>, cudaFuncAttributeMaxDynamicSharedMemorySize, smem64);

    int nb_scan = (n + 1023) >> 10;

    int gemm_blocks = (n + 127) / 128;
    int agg_blocks  = (int)(((long long)n * 32 + 255) / 256);

    // CSR build + dinv. Order chosen so launch #4 (ncu sample) = k_gemm layer 1.
    k_zero <<<(n + 255) / 256, 256>>>(n);                  // 1
    k_count<<<(e + 255) / 256, 256>>>(dstp, e);            // 2
    k_scan1<<<nb_scan, 1024>>>(n);                         // 3 (also computes dinv)
    k_gemm<HH><<<gemm_blocks, 256, smem128>>>(x, W1, n, 0);// 4  <-- profiled
    k_scan2<<<1, 128>>>(nb_scan, n);                       // 5
    k_scan3<<<(n + 255) / 256, 256>>>(n);                  // 6
    k_fill <<<(e + 255) / 256, 256>>>(srcp, dstp, e);      // 7

    // layer 1 aggregate
    k_agg<HH, 0><<<agg_blocks, 256>>>(b1, nullptr, n);
    // layer 2
    k_gemm<HH><<<gemm_blocks, 256, smem128>>>(x, W2, n, 1);
    k_agg<HH, 0><<<agg_blocks, 256>>>(b2, nullptr, n);
    // layer 3
    k_gemm<OUTC><<<gemm_blocks, 256, smem64>>>(x, W3, n, 1);
    k_agg<OUTC, 1><<<agg_blocks, 256>>>(b3, out, n);
}

// round 5
// speedup vs baseline: 1.7478x; 1.0105x over previous
#include <cuda_runtime.h>
#include <cstdint>

#define NN   100000
#define EE   1600000
#define FIN  128
#define HH   128
#define OUTC 64

// ---------------- scratch (no allocation allowed) ----------------
__device__ __align__(16) int   g_cnt[NN];
__device__ __align__(16) int   g_rowptr[NN + 1];
__device__ __align__(16) int   g_cursor[NN];
__device__ __align__(16) int   g_bsum[256];
__device__ __align__(16) float g_dinv[NN];
__device__ __align__(16) int   g_csr_src[EE];
__device__ __align__(16) float g_t[(size_t)NN * HH];   // GEMM output (pre-scaled by dinv)
__device__ __align__(16) float g_h[(size_t)NN * HH];   // layer activation

// ================= CSR construction =================
__global__ void k_zero(int n) {
    int i = blockIdx.x * blockDim.x + threadIdx.x;
    if (i < n) g_cnt[i] = 0;
}
__global__ void k_count(const int* __restrict__ dst, int e) {
    int i = blockIdx.x * blockDim.x + threadIdx.x;
    if (i < e) atomicAdd(&g_cnt[dst[i]], 1);
}
// per-block exclusive scan (1024 elems/block) + dinv (needs only cnt)
__global__ void k_scan1(int n) {
    __shared__ int sh[1024];
    int tid = threadIdx.x;
    int i = blockIdx.x * 1024 + tid;
    int v = (i < n) ? g_cnt[i] : 0;
    sh[tid] = v;
    __syncthreads();
#pragma unroll
    for (int off = 1; off < 1024; off <<= 1) {
        int t = (tid >= off) ? sh[tid - off] : 0;
        __syncthreads();
        sh[tid] += t;
        __syncthreads();
    }
    if (i < n) {
        g_rowptr[i] = sh[tid] - v;                 // exclusive, local
        g_dinv[i]   = rsqrtf(1.0f + (float)v);     // +1 self-loop
    }
    if (tid == 1023) g_bsum[blockIdx.x] = sh[1023];
}
// parallel scan of block sums (nb <= 128), one 128-thread block
__global__ void k_scan2(int nb, int n) {
    __shared__ int sh[128];
    int tid = threadIdx.x;
    int v = (tid < nb) ? g_bsum[tid] : 0;
    sh[tid] = v;
    __syncthreads();
#pragma unroll
    for (int off = 1; off < 128; off <<= 1) {
        int t = (tid >= off) ? sh[tid - off] : 0;
        __syncthreads();
        sh[tid] += t;
        __syncthreads();
    }
    if (tid < nb) g_bsum[tid] = sh[tid] - v;   // exclusive
    if (tid == 127) g_rowptr[n] = sh[127];     // total
}
__global__ void k_scan3(int n) {   // add block offsets, init cursor
    int i = blockIdx.x * blockDim.x + threadIdx.x;
    if (i >= n) return;
    int v = g_rowptr[i] + g_bsum[i >> 10];
    g_rowptr[i] = v;
    g_cursor[i] = v;
}
__global__ void k_fill(const int* __restrict__ src, const int* __restrict__ dst, int e) {
    int i = blockIdx.x * blockDim.x + threadIdx.x;
    if (i >= e) return;
    int d = dst[i];
    int pos = atomicAdd(&g_cursor[d], 1);
    g_csr_src[pos] = src[i];
}

// ================= GEMM: g_t[M,DOUT] = dinv[row] * (A[M,128] @ W[128,DOUT]) =================
// 512 threads, 128-row tile, per-thread 4x(DOUT/16) register block.
// Thread grid 32x16: tr=tid>>4 owns rows r0=tr*4.., tc=tid&15 owns cols c0=tc*TC..
template<int DOUT>
__global__ __launch_bounds__(512, 1)
void k_gemm(const float* __restrict__ Ax, const float* __restrict__ W,
            int M, int from_h) {
    constexpr int DIN = 128;
    constexpr int AST = DIN + 4;           // padded stride (multiple of 4 -> float4 ok)
    extern __shared__ float sm[];
    float* Ws = sm;                        // DIN*DOUT
    float* As = sm + DIN * DOUT;           // 128*AST

    const float* A = from_h ? g_h : Ax;
    int tid  = threadIdx.x;
    int row0 = blockIdx.x * 128;

    for (int i = tid; i < DIN * DOUT / 4; i += 512)
        ((float4*)Ws)[i] = ((const float4*)W)[i];

    for (int i = tid; i < 128 * 32; i += 512) {
        int r  = i >> 5;
        int c4 = i & 31;
        int gr = row0 + r;
        float4 v = make_float4(0.f, 0.f, 0.f, 0.f);
        if (gr < M) v = ((const float4*)A)[(size_t)gr * 32 + c4];
        *(float4*)(As + r * AST + c4 * 4) = v;
    }
    __syncthreads();

    constexpr int TC = DOUT / 16;          // 8 or 4 cols/thread
    int r0 = (tid >> 4) * 4;
    int c0 = (tid & 15) * TC;

    float acc[4][TC];
#pragma unroll
    for (int i = 0; i < 4; i++)
#pragma unroll
        for (int c = 0; c < TC; c++) acc[i][c] = 0.f;

    for (int kk = 0; kk < DIN; kk += 4) {
        float4 av[4];
#pragma unroll
        for (int i = 0; i < 4; i++)
            av[i] = *(const float4*)&As[(r0 + i) * AST + kk];
#pragma unroll
        for (int j = 0; j < 4; j++) {
            float b[TC];
#pragma unroll
            for (int c = 0; c < TC; c += 4)
                *(float4*)&b[c] = *(const float4*)&Ws[(kk + j) * DOUT + c0 + c];
#pragma unroll
            for (int i = 0; i < 4; i++) {
                float a = (j == 0) ? av[i].x : (j == 1) ? av[i].y
                        : (j == 2) ? av[i].z : av[i].w;
#pragma unroll
                for (int c = 0; c < TC; c++)
                    acc[i][c] = fmaf(a, b[c], acc[i][c]);
            }
        }
    }

#pragma unroll
    for (int i = 0; i < 4; i++) {
        int gr = row0 + r0 + i;
        if (gr < M) {
            float s = g_dinv[gr];
#pragma unroll
            for (int c = 0; c < TC; c += 4)
                *(float4*)&g_t[(size_t)gr * DOUT + c0 + c] =
                    make_float4(s * acc[i][c], s * acc[i][c+1],
                                s * acc[i][c+2], s * acc[i][c+3]);
        }
    }
}

// ================= Aggregation (warp per node), fused epilogue =================
// acc = t[i] + sum_{s in N(i)} t[s];  res = dinv[i]*acc + bias
// MODE 0: relu -> g_h      MODE 1: log_softmax -> out (DOUT=64)
template<int DOUT, int MODE>
__global__ void k_agg(const float* __restrict__ bias, float* __restrict__ out, int n) {
    int w    = (blockIdx.x * blockDim.x + threadIdx.x) >> 5;
    int lane = threadIdx.x & 31;
    if (w >= n) return;
    constexpr int VF = DOUT / 32;          // 4 or 2 floats per lane

    float acc[VF];
    {   // self term
        const float* p = g_t + (size_t)w * DOUT + lane * VF;
        if (VF == 4) { float4 v = *(const float4*)p; acc[0]=v.x; acc[1]=v.y; acc[2]=v.z; acc[3]=v.w; }
        else         { float2 v = *(const float2*)p; acc[0]=v.x; acc[1]=v.y; }
    }

    int beg = g_rowptr[w], end = g_rowptr[w + 1];
    for (int jb = beg; jb < end; jb += 32) {
        int myj = jb + lane;
        int ms  = (myj < end) ? g_csr_src[myj] : 0;
        int cnt = min(32, end - jb);
        int k = 0;
        for (; k + 4 <= cnt; k += 4) {
            int s0 = __shfl_sync(0xffffffffu, ms, k);
            int s1 = __shfl_sync(0xffffffffu, ms, k + 1);
            int s2 = __shfl_sync(0xffffffffu, ms, k + 2);
            int s3 = __shfl_sync(0xffffffffu, ms, k + 3);
            if (VF == 4) {
                float4 v0 = *(const float4*)(g_t + (size_t)s0 * DOUT + lane * 4);
                float4 v1 = *(const float4*)(g_t + (size_t)s1 * DOUT + lane * 4);
                float4 v2 = *(const float4*)(g_t + (size_t)s2 * DOUT + lane * 4);
                float4 v3 = *(const float4*)(g_t + (size_t)s3 * DOUT + lane * 4);
                acc[0] += (v0.x + v1.x) + (v2.x + v3.x);
                acc[1] += (v0.y + v1.y) + (v2.y + v3.y);
                acc[2] += (v0.z + v1.z) + (v2.z + v3.z);
                acc[3] += (v0.w + v1.w) + (v2.w + v3.w);
            } else {
                float2 v0 = *(const float2*)(g_t + (size_t)s0 * DOUT + lane * 2);
                float2 v1 = *(const float2*)(g_t + (size_t)s1 * DOUT + lane * 2);
                float2 v2 = *(const float2*)(g_t + (size_t)s2 * DOUT + lane * 2);
                float2 v3 = *(const float2*)(g_t + (size_t)s3 * DOUT + lane * 2);
                acc[0] += (v0.x + v1.x) + (v2.x + v3.x);
                acc[1] += (v0.y + v1.y) + (v2.y + v3.y);
            }
        }
        for (; k < cnt; k++) {
            int s = __shfl_sync(0xffffffffu, ms, k);
            if (VF == 4) {
                float4 v = *(const float4*)(g_t + (size_t)s * DOUT + lane * 4);
                acc[0] += v.x; acc[1] += v.y; acc[2] += v.z; acc[3] += v.w;
            } else {
                float2 v = *(const float2*)(g_t + (size_t)s * DOUT + lane * 2);
                acc[0] += v.x; acc[1] += v.y;
            }
        }
    }

    float di = g_dinv[w];
    if (MODE == 0) {   // bias + relu -> g_h
        float4 bb = ((const float4*)bias)[lane];
        float4 r;
        r.x = fmaxf(fmaf(di, acc[0], bb.x), 0.f);
        r.y = fmaxf(fmaf(di, acc[1], bb.y), 0.f);
        r.z = fmaxf(fmaf(di, acc[2], bb.z), 0.f);
        r.w = fmaxf(fmaf(di, acc[3], bb.w), 0.f);
        *(float4*)(g_h + (size_t)w * DOUT + lane * 4) = r;
    } else {           // bias + log_softmax -> out (64 cols)
        float2 bb = ((const float2*)bias)[lane];
        float vx = fmaf(di, acc[0], bb.x);
        float vy = fmaf(di, acc[1], bb.y);
        float m = fmaxf(vx, vy);
#pragma unroll
        for (int o = 16; o; o >>= 1) m = fmaxf(m, __shfl_xor_sync(0xffffffffu, m, o));
        float sum = expf(vx - m) + expf(vy - m);
#pragma unroll
        for (int o = 16; o; o >>= 1) sum += __shfl_xor_sync(0xffffffffu, sum, o);
        float lse = m + logf(sum);
        *(float2*)(out + (size_t)w * 64 + lane * 2) = make_float2(vx - lse, vy - lse);
    }
}

// ================= launch =================
extern "C" void kernel_launch(void* const* d_in, const int* in_sizes, int n_in,
                              void* d_out, int out_size) {
    const float* x   = (const float*)d_in[0];
    const int*   ei  = (const int*)d_in[1];     // int32 (JAX x64 disabled)
    const float* W1  = (const float*)d_in[2];
    const float* b1  = (const float*)d_in[3];
    const float* W2  = (const float*)d_in[4];
    const float* b2  = (const float*)d_in[5];
    const float* W3  = (const float*)d_in[6];
    const float* b3  = (const float*)d_in[7];
    float* out = (float*)d_out;

    int n = in_sizes[0] / FIN;
    int e = in_sizes[1] / 2;
    const int* srcp = ei;
    const int* dstp = ei + e;

    const int smem128 = (FIN * HH   + 128 * (FIN + 4)) * sizeof(float); // ~131 KB
    const int smem64  = (FIN * OUTC + 128 * (FIN + 4)) * sizeof(float); // ~99 KB
    cudaFuncSetAttribute(k_gemm<HH>,   cudaFuncAttributeMaxDynamicSharedMemorySize, smem128);
    cudaFuncSetAttribute(k_gemm<OUTC>, cudaFuncAttributeMaxDynamicSharedMemorySize, smem64);

    int nb_scan = (n + 1023) >> 10;

    int gemm_blocks = (n + 127) / 128;
    int agg_blocks  = (int)(((long long)n * 32 + 255) / 256);

    // CSR build + dinv. Order chosen so launch #4 (ncu sample) = k_gemm layer 1.
    k_zero <<<(n + 255) / 256, 256>>>(n);                  // 1
    k_count<<<(e + 255) / 256, 256>>>(dstp, e);            // 2
    k_scan1<<<nb_scan, 1024>>>(n);                         // 3 (also computes dinv)
    k_gemm<HH><<<gemm_blocks, 512, smem128>>>(x, W1, n, 0);// 4  <-- profiled
    k_scan2<<<1, 128>>>(nb_scan, n);                       // 5
    k_scan3<<<(n + 255) / 256, 256>>>(n);                  // 6
    k_fill <<<(e + 255) / 256, 256>>>(srcp, dstp, e);      // 7

    // layer 1 aggregate
    k_agg<HH, 0><<<agg_blocks, 256>>>(b1, nullptr, n);
    // layer 2
    k_gemm<HH><<<gemm_blocks, 512, smem128>>>(x, W2, n, 1);
    k_agg<HH, 0><<<agg_blocks, 256>>>(b2, nullptr, n);
    // layer 3
    k_gemm<OUTC><<<gemm_blocks, 512, smem64>>>(x, W3, n, 1);
    k_agg<OUTC, 1><<<agg_blocks, 256>>>(b3, out, n);
}

// round 6
// speedup vs baseline: 2.0223x; 1.1571x over previous
#include <cuda_runtime.h>
#include <cstdint>

#define NN   100000
#define EE   1600000
#define FIN  128
#define HH   128
#define OUTC 64

// ---------------- scratch (no allocation allowed) ----------------
__device__ __align__(16) int   g_cnt[NN];
__device__ __align__(16) int   g_rowptr[NN + 1];
__device__ __align__(16) int   g_cursor[NN];
__device__ __align__(16) int   g_bsum[256];
__device__ __align__(16) float g_dinv[NN];
__device__ __align__(16) int   g_csr_src[EE];
__device__ __align__(16) float g_t[(size_t)NN * HH];   // GEMM output (pre-scaled by dinv)
__device__ __align__(16) float g_h[(size_t)NN * HH];   // layer activation

// ================= CSR construction =================
__global__ void k_zero(int n) {
    int i = blockIdx.x * blockDim.x + threadIdx.x;
    if (i < n) g_cnt[i] = 0;
}
__global__ void k_count(const int* __restrict__ dst, int e) {
    int i = blockIdx.x * blockDim.x + threadIdx.x;
    if (i < e) atomicAdd(&g_cnt[dst[i]], 1);
}
__global__ void k_scan1(int n) {
    __shared__ int sh[1024];
    int tid = threadIdx.x;
    int i = blockIdx.x * 1024 + tid;
    int v = (i < n) ? g_cnt[i] : 0;
    sh[tid] = v;
    __syncthreads();
#pragma unroll
    for (int off = 1; off < 1024; off <<= 1) {
        int t = (tid >= off) ? sh[tid - off] : 0;
        __syncthreads();
        sh[tid] += t;
        __syncthreads();
    }
    if (i < n) {
        g_rowptr[i] = sh[tid] - v;                 // exclusive, local
        g_dinv[i]   = rsqrtf(1.0f + (float)v);     // +1 self-loop
    }
    if (tid == 1023) g_bsum[blockIdx.x] = sh[1023];
}
__global__ void k_scan2(int nb, int n) {
    __shared__ int sh[128];
    int tid = threadIdx.x;
    int v = (tid < nb) ? g_bsum[tid] : 0;
    sh[tid] = v;
    __syncthreads();
#pragma unroll
    for (int off = 1; off < 128; off <<= 1) {
        int t = (tid >= off) ? sh[tid - off] : 0;
        __syncthreads();
        sh[tid] += t;
        __syncthreads();
    }
    if (tid < nb) g_bsum[tid] = sh[tid] - v;
    if (tid == 127) g_rowptr[n] = sh[127];
}
__global__ void k_scan3(int n) {
    int i = blockIdx.x * blockDim.x + threadIdx.x;
    if (i >= n) return;
    int v = g_rowptr[i] + g_bsum[i >> 10];
    g_rowptr[i] = v;
    g_cursor[i] = v;
}
__global__ void k_fill(const int* __restrict__ src, const int* __restrict__ dst, int e) {
    int i = blockIdx.x * blockDim.x + threadIdx.x;
    if (i >= e) return;
    int d = dst[i];
    int pos = atomicAdd(&g_cursor[d], 1);
    g_csr_src[pos] = src[i];
}

// ================= TF32 helpers =================
__device__ __forceinline__ void split_tf32(float v, float& hi, float& lo) {
    hi = __uint_as_float(__float_as_uint(v) & 0xFFFFE000u);  // exact tf32 truncation
    lo = v - hi;                                             // exact residual
}
__device__ __forceinline__ void mma_tf32(float c[4], const float a[4], const float b[2]) {
    asm volatile(
        "mma.sync.aligned.m16n8k8.row.col.f32.tf32.tf32.f32 "
        "{%0,%1,%2,%3}, {%4,%5,%6,%7}, {%8,%9}, {%0,%1,%2,%3};"
        : "+f"(c[0]), "+f"(c[1]), "+f"(c[2]), "+f"(c[3])
        : "r"(__float_as_uint(a[0])), "r"(__float_as_uint(a[1])),
          "r"(__float_as_uint(a[2])), "r"(__float_as_uint(a[3])),
          "r"(__float_as_uint(b[0])), "r"(__float_as_uint(b[1])));
}

// ================= GEMM: g_t[M,DOUT] = dinv[row] * (A[M,128] @ W[128,DOUT]) =================
// 256 threads (8 warps, 4m x 2n). CTA tile 128 x DOUT. Error-compensated TF32 mma.
// Per warp: M_w=32 (2 m16 tiles), N_w=DOUT/2 (DOUT/16 n8 tiles).
template<int DOUT>
__global__ __launch_bounds__(256, 1)
void k_gemm(const float* __restrict__ Ax, const float* __restrict__ W,
            int M, int from_h) {
    constexpr int DIN = 128;
    constexpr int AST = DIN + 4;      // A smem stride: frag banks 4r+c -> conflict-free
    constexpr int WST = DOUT + 8;     // W smem stride: frag banks 8k+n -> conflict-free
    constexpr int NT  = DOUT / 16;    // n8-tiles per warp (8 or 4)

    extern __shared__ float sm[];
    float* As = sm;                   // [128][AST]
    float* Ws = sm + 128 * AST;       // [128][WST]  row=k, col=n

    const float* A = from_h ? g_h : Ax;
    int tid  = threadIdx.x;
    int row0 = blockIdx.x * 128;

    // stage W
    for (int i = tid; i < DIN * (DOUT / 4); i += 256) {
        int r  = i / (DOUT / 4);
        int c4 = i % (DOUT / 4);
        *(float4*)(Ws + r * WST + c4 * 4) = ((const float4*)W)[i];
    }
    // stage A (zero-fill OOB rows)
    for (int i = tid; i < 128 * 32; i += 256) {
        int r  = i >> 5;
        int c4 = i & 31;
        int gr = row0 + r;
        float4 v = make_float4(0.f, 0.f, 0.f, 0.f);
        if (gr < M) v = ((const float4*)A)[(size_t)gr * 32 + c4];
        *(float4*)(As + r * AST + c4 * 4) = v;
    }
    __syncthreads();

    int warp = tid >> 5, lane = tid & 31;
    int wm = warp & 3;                 // 0..3
    int wn = warp >> 2;                // 0..1
    int g  = lane >> 2;                // group id 0..7
    int t  = lane & 3;                 // thread in group 0..3
    int mbase = wm * 32;
    int nbase = wn * (DOUT / 2);

    float acc[2][NT][4];
#pragma unroll
    for (int i = 0; i < 2; i++)
#pragma unroll
        for (int j = 0; j < NT; j++)
#pragma unroll
            for (int q = 0; q < 4; q++) acc[i][j][q] = 0.f;

#pragma unroll 1
    for (int kk = 0; kk < DIN; kk += 8) {
        float ahi[2][4], alo[2][4];
#pragma unroll
        for (int i = 0; i < 2; i++) {
            const float* ap = As + (mbase + i * 16 + g) * AST + kk + t;
            float a0 = ap[0];
            float a1 = ap[8 * AST];
            float a2 = ap[4];
            float a3 = ap[8 * AST + 4];
            split_tf32(a0, ahi[i][0], alo[i][0]);
            split_tf32(a1, ahi[i][1], alo[i][1]);
            split_tf32(a2, ahi[i][2], alo[i][2]);
            split_tf32(a3, ahi[i][3], alo[i][3]);
        }
        float bhi[NT][2], blo[NT][2];
#pragma unroll
        for (int j = 0; j < NT; j++) {
            const float* bp = Ws + (kk + t) * WST + nbase + j * 8 + g;
            float b0 = bp[0];
            float b1 = bp[4 * WST];
            split_tf32(b0, bhi[j][0], blo[j][0]);
            split_tf32(b1, bhi[j][1], blo[j][1]);
        }
#pragma unroll
        for (int i = 0; i < 2; i++)
#pragma unroll
            for (int j = 0; j < NT; j++) {
                mma_tf32(acc[i][j], ahi[i], bhi[j]);
                mma_tf32(acc[i][j], ahi[i], blo[j]);
                mma_tf32(acc[i][j], alo[i], bhi[j]);
            }
    }

    // epilogue: scale by dinv, store float2 pairs
#pragma unroll
    for (int i = 0; i < 2; i++) {
        int r_lo = row0 + mbase + i * 16 + g;
        int r_hi = r_lo + 8;
        float s_lo = (r_lo < M) ? g_dinv[r_lo] : 0.f;
        float s_hi = (r_hi < M) ? g_dinv[r_hi] : 0.f;
#pragma unroll
        for (int j = 0; j < NT; j++) {
            int col = nbase + j * 8 + 2 * t;
            if (r_lo < M)
                *(float2*)&g_t[(size_t)r_lo * DOUT + col] =
                    make_float2(s_lo * acc[i][j][0], s_lo * acc[i][j][1]);
            if (r_hi < M)
                *(float2*)&g_t[(size_t)r_hi * DOUT + col] =
                    make_float2(s_hi * acc[i][j][2], s_hi * acc[i][j][3]);
        }
    }
}

// ================= Aggregation (warp per node), fused epilogue =================
template<int DOUT, int MODE>
__global__ void k_agg(const float* __restrict__ bias, float* __restrict__ out, int n) {
    int w    = (blockIdx.x * blockDim.x + threadIdx.x) >> 5;
    int lane = threadIdx.x & 31;
    if (w >= n) return;
    constexpr int VF = DOUT / 32;

    float acc[VF];
    {
        const float* p = g_t + (size_t)w * DOUT + lane * VF;
        if (VF == 4) { float4 v = *(const float4*)p; acc[0]=v.x; acc[1]=v.y; acc[2]=v.z; acc[3]=v.w; }
        else         { float2 v = *(const float2*)p; acc[0]=v.x; acc[1]=v.y; }
    }

    int beg = g_rowptr[w], end = g_rowptr[w + 1];
    for (int jb = beg; jb < end; jb += 32) {
        int myj = jb + lane;
        int ms  = (myj < end) ? g_csr_src[myj] : 0;
        int cnt = min(32, end - jb);
        int k = 0;
        for (; k + 4 <= cnt; k += 4) {
            int s0 = __shfl_sync(0xffffffffu, ms, k);
            int s1 = __shfl_sync(0xffffffffu, ms, k + 1);
            int s2 = __shfl_sync(0xffffffffu, ms, k + 2);
            int s3 = __shfl_sync(0xffffffffu, ms, k + 3);
            if (VF == 4) {
                float4 v0 = *(const float4*)(g_t + (size_t)s0 * DOUT + lane * 4);
                float4 v1 = *(const float4*)(g_t + (size_t)s1 * DOUT + lane * 4);
                float4 v2 = *(const float4*)(g_t + (size_t)s2 * DOUT + lane * 4);
                float4 v3 = *(const float4*)(g_t + (size_t)s3 * DOUT + lane * 4);
                acc[0] += (v0.x + v1.x) + (v2.x + v3.x);
                acc[1] += (v0.y + v1.y) + (v2.y + v3.y);
                acc[2] += (v0.z + v1.z) + (v2.z + v3.z);
                acc[3] += (v0.w + v1.w) + (v2.w + v3.w);
            } else {
                float2 v0 = *(const float2*)(g_t + (size_t)s0 * DOUT + lane * 2);
                float2 v1 = *(const float2*)(g_t + (size_t)s1 * DOUT + lane * 2);
                float2 v2 = *(const float2*)(g_t + (size_t)s2 * DOUT + lane * 2);
                float2 v3 = *(const float2*)(g_t + (size_t)s3 * DOUT + lane * 2);
                acc[0] += (v0.x + v1.x) + (v2.x + v3.x);
                acc[1] += (v0.y + v1.y) + (v2.y + v3.y);
            }
        }
        for (; k < cnt; k++) {
            int s = __shfl_sync(0xffffffffu, ms, k);
            if (VF == 4) {
                float4 v = *(const float4*)(g_t + (size_t)s * DOUT + lane * 4);
                acc[0] += v.x; acc[1] += v.y; acc[2] += v.z; acc[3] += v.w;
            } else {
                float2 v = *(const float2*)(g_t + (size_t)s * DOUT + lane * 2);
                acc[0] += v.x; acc[1] += v.y;
            }
        }
    }

    float di = g_dinv[w];
    if (MODE == 0) {
        float4 bb = ((const float4*)bias)[lane];
        float4 r;
        r.x = fmaxf(fmaf(di, acc[0], bb.x), 0.f);
        r.y = fmaxf(fmaf(di, acc[1], bb.y), 0.f);
        r.z = fmaxf(fmaf(di, acc[2], bb.z), 0.f);
        r.w = fmaxf(fmaf(di, acc[3], bb.w), 0.f);
        *(float4*)(g_h + (size_t)w * DOUT + lane * 4) = r;
    } else {
        float2 bb = ((const float2*)bias)[lane];
        float vx = fmaf(di, acc[0], bb.x);
        float vy = fmaf(di, acc[1], bb.y);
        float m = fmaxf(vx, vy);
#pragma unroll
        for (int o = 16; o; o >>= 1) m = fmaxf(m, __shfl_xor_sync(0xffffffffu, m, o));
        float sum = expf(vx - m) + expf(vy - m);
#pragma unroll
        for (int o = 16; o; o >>= 1) sum += __shfl_xor_sync(0xffffffffu, sum, o);
        float lse = m + logf(sum);
        *(float2*)(out + (size_t)w * 64 + lane * 2) = make_float2(vx - lse, vy - lse);
    }
}

// ================= launch =================
extern "C" void kernel_launch(void* const* d_in, const int* in_sizes, int n_in,
                              void* d_out, int out_size) {
    const float* x   = (const float*)d_in[0];
    const int*   ei  = (const int*)d_in[1];     // int32 (JAX x64 disabled)
    const float* W1  = (const float*)d_in[2];
    const float* b1  = (const float*)d_in[3];
    const float* W2  = (const float*)d_in[4];
    const float* b2  = (const float*)d_in[5];
    const float* W3  = (const float*)d_in[6];
    const float* b3  = (const float*)d_in[7];
    float* out = (float*)d_out;

    int n = in_sizes[0] / FIN;
    int e = in_sizes[1] / 2;
    const int* srcp = ei;
    const int* dstp = ei + e;

    const int smem128 = (128 * (FIN + 4) + 128 * (HH   + 8)) * sizeof(float); // ~134 KB
    const int smem64  = (128 * (FIN + 4) + 128 * (OUTC + 8)) * sizeof(float); // ~102 KB
    cudaFuncSetAttribute(k_gemm<HH>,   cudaFuncAttributeMaxDynamicSharedMemorySize, smem128);
    cudaFuncSetAttribute(k_gemm<OUTC>, cudaFuncAttributeMaxDynamicSharedMemorySize, smem64);

    int nb_scan = (n + 1023) >> 10;
    int gemm_blocks = (n + 127) / 128;
    int agg_blocks  = (int)(((long long)n * 32 + 255) / 256);

    // CSR build + dinv. Order chosen so launch #4 (ncu sample) = k_gemm layer 1.
    k_zero <<<(n + 255) / 256, 256>>>(n);                  // 1
    k_count<<<(e + 255) / 256, 256>>>(dstp, e);            // 2
    k_scan1<<<nb_scan, 1024>>>(n);                         // 3
    k_gemm<HH><<<gemm_blocks, 256, smem128>>>(x, W1, n, 0);// 4  <-- profiled
    k_scan2<<<1, 128>>>(nb_scan, n);                       // 5
    k_scan3<<<(n + 255) / 256, 256>>>(n);                  // 6
    k_fill <<<(e + 255) / 256, 256>>>(srcp, dstp, e);      // 7

    // layer 1 aggregate
    k_agg<HH, 0><<<agg_blocks, 256>>>(b1, nullptr, n);
    // layer 2
    k_gemm<HH><<<gemm_blocks, 256, smem128>>>(x, W2, n, 1);
    k_agg<HH, 0><<<agg_blocks, 256>>>(b2, nullptr, n);
    // layer 3
    k_gemm<OUTC><<<gemm_blocks, 256, smem64>>>(x, W3, n, 1);
    k_agg<OUTC, 1><<<agg_blocks, 256>>>(b3, out, n);
}

// round 7
// speedup vs baseline: 2.3462x; 1.1601x over previous
#include <cuda_runtime.h>
#include <cstdint>

#define NN   100000
#define EE   1600000
#define FIN  128
#define HH   128
#define OUTC 64

// ---------------- scratch (no allocation allowed) ----------------
__device__ __align__(16) int   g_cnt[NN];
__device__ __align__(16) int   g_rowptr[NN + 1];
__device__ __align__(16) int   g_cursor[NN];
__device__ __align__(16) int   g_bsum[256];
__device__ __align__(16) float g_dinv[NN];
__device__ __align__(16) int   g_csr_src[EE];
__device__ __align__(16) float g_t[(size_t)NN * HH];   // GEMM output (pre-scaled by dinv)
__device__ __align__(16) float g_h[(size_t)NN * HH];   // layer activation

// ================= CSR construction =================
__global__ void k_zero(int n) {
    int i = blockIdx.x * blockDim.x + threadIdx.x;
    if (i < n) g_cnt[i] = 0;
}
__global__ void k_count(const int* __restrict__ dst, int e) {
    int i = blockIdx.x * blockDim.x + threadIdx.x;
    if (i < e) atomicAdd(&g_cnt[dst[i]], 1);
}
__global__ void k_scan1(int n) {
    __shared__ int sh[1024];
    int tid = threadIdx.x;
    int i = blockIdx.x * 1024 + tid;
    int v = (i < n) ? g_cnt[i] : 0;
    sh[tid] = v;
    __syncthreads();
#pragma unroll
    for (int off = 1; off < 1024; off <<= 1) {
        int t = (tid >= off) ? sh[tid - off] : 0;
        __syncthreads();
        sh[tid] += t;
        __syncthreads();
    }
    if (i < n) {
        g_rowptr[i] = sh[tid] - v;                 // exclusive, local
        g_dinv[i]   = rsqrtf(1.0f + (float)v);     // +1 self-loop
    }
    if (tid == 1023) g_bsum[blockIdx.x] = sh[1023];
}
__global__ void k_scan2(int nb, int n) {
    __shared__ int sh[128];
    int tid = threadIdx.x;
    int v = (tid < nb) ? g_bsum[tid] : 0;
    sh[tid] = v;
    __syncthreads();
#pragma unroll
    for (int off = 1; off < 128; off <<= 1) {
        int t = (tid >= off) ? sh[tid - off] : 0;
        __syncthreads();
        sh[tid] += t;
        __syncthreads();
    }
    if (tid < nb) g_bsum[tid] = sh[tid] - v;
    if (tid == 127) g_rowptr[n] = sh[127];
}
__global__ void k_scan3(int n) {
    int i = blockIdx.x * blockDim.x + threadIdx.x;
    if (i >= n) return;
    int v = g_rowptr[i] + g_bsum[i >> 10];
    g_rowptr[i] = v;
    g_cursor[i] = v;
}
__global__ void k_fill(const int* __restrict__ src, const int* __restrict__ dst, int e) {
    int i = blockIdx.x * blockDim.x + threadIdx.x;
    if (i >= e) return;
    int d = dst[i];
    int pos = atomicAdd(&g_cursor[d], 1);
    g_csr_src[pos] = src[i];
}

// ================= TF32 helpers =================
__device__ __forceinline__ void split_tf32(float v, float& hi, float& lo) {
    hi = __uint_as_float(__float_as_uint(v) & 0xFFFFE000u);  // exact tf32 truncation
    lo = v - hi;                                             // exact residual
}
__device__ __forceinline__ void mma_tf32(float c[4], const float a[4], const float b[2]) {
    asm volatile(
        "mma.sync.aligned.m16n8k8.row.col.f32.tf32.tf32.f32 "
        "{%0,%1,%2,%3}, {%4,%5,%6,%7}, {%8,%9}, {%0,%1,%2,%3};"
        : "+f"(c[0]), "+f"(c[1]), "+f"(c[2]), "+f"(c[3])
        : "r"(__float_as_uint(a[0])), "r"(__float_as_uint(a[1])),
          "r"(__float_as_uint(a[2])), "r"(__float_as_uint(a[3])),
          "r"(__float_as_uint(b[0])), "r"(__float_as_uint(b[1])));
}

// ================= GEMM: g_t[M,DOUT] = dinv[row] * (A[M,128] @ W[128,DOUT]) =================
// 512 threads (16 warps, 4m x 4n). CTA tile 128 x DOUT. Error-compensated 3xTF32 mma.
// Per warp: 32 rows (2 m16 tiles) x DOUT/4 cols (NT = DOUT/32 n8-tiles).
template<int DOUT>
__global__ __launch_bounds__(512, 1)
void k_gemm(const float* __restrict__ Ax, const float* __restrict__ W,
            int M, int from_h) {
    constexpr int DIN = 128;
    constexpr int AST = DIN + 4;      // A smem stride: frag banks 4r+c -> conflict-free
    constexpr int WST = DOUT + 8;     // W smem stride: frag banks 8k+n -> conflict-free
    constexpr int NT  = DOUT / 32;    // n8-tiles per warp (4 or 2)

    extern __shared__ float sm[];
    float* As = sm;                   // [128][AST]
    float* Ws = sm + 128 * AST;       // [128][WST]  row=k, col=n

    const float* A = from_h ? g_h : Ax;
    int tid  = threadIdx.x;
    int row0 = blockIdx.x * 128;

    // stage W
    for (int i = tid; i < DIN * (DOUT / 4); i += 512) {
        int r  = i / (DOUT / 4);
        int c4 = i % (DOUT / 4);
        *(float4*)(Ws + r * WST + c4 * 4) = ((const float4*)W)[i];
    }
    // stage A (zero-fill OOB rows)
    for (int i = tid; i < 128 * 32; i += 512) {
        int r  = i >> 5;
        int c4 = i & 31;
        int gr = row0 + r;
        float4 v = make_float4(0.f, 0.f, 0.f, 0.f);
        if (gr < M) v = ((const float4*)A)[(size_t)gr * 32 + c4];
        *(float4*)(As + r * AST + c4 * 4) = v;
    }
    __syncthreads();

    int warp = tid >> 5, lane = tid & 31;
    int wm = warp & 3;                 // 0..3
    int wn = warp >> 2;                // 0..3
    int g  = lane >> 2;                // group id 0..7
    int t  = lane & 3;                 // thread in group 0..3
    int mbase = wm * 32;
    int nbase = wn * (DOUT / 4);

    float acc[2][NT][4];
#pragma unroll
    for (int i = 0; i < 2; i++)
#pragma unroll
        for (int j = 0; j < NT; j++)
#pragma unroll
            for (int q = 0; q < 4; q++) acc[i][j][q] = 0.f;

#pragma unroll 2
    for (int kk = 0; kk < DIN; kk += 8) {
        float ahi[2][4], alo[2][4];
#pragma unroll
        for (int i = 0; i < 2; i++) {
            const float* ap = As + (mbase + i * 16 + g) * AST + kk + t;
            float a0 = ap[0];
            float a1 = ap[8 * AST];
            float a2 = ap[4];
            float a3 = ap[8 * AST + 4];
            split_tf32(a0, ahi[i][0], alo[i][0]);
            split_tf32(a1, ahi[i][1], alo[i][1]);
            split_tf32(a2, ahi[i][2], alo[i][2]);
            split_tf32(a3, ahi[i][3], alo[i][3]);
        }
        float bhi[NT][2], blo[NT][2];
#pragma unroll
        for (int j = 0; j < NT; j++) {
            const float* bp = Ws + (kk + t) * WST + nbase + j * 8 + g;
            float b0 = bp[0];
            float b1 = bp[4 * WST];
            split_tf32(b0, bhi[j][0], blo[j][0]);
            split_tf32(b1, bhi[j][1], blo[j][1]);
        }
#pragma unroll
        for (int i = 0; i < 2; i++)
#pragma unroll
            for (int j = 0; j < NT; j++) {
                mma_tf32(acc[i][j], ahi[i], bhi[j]);
                mma_tf32(acc[i][j], ahi[i], blo[j]);
                mma_tf32(acc[i][j], alo[i], bhi[j]);
            }
    }

    // epilogue: scale by dinv, store float2 pairs
#pragma unroll
    for (int i = 0; i < 2; i++) {
        int r_lo = row0 + mbase + i * 16 + g;
        int r_hi = r_lo + 8;
        float s_lo = (r_lo < M) ? g_dinv[r_lo] : 0.f;
        float s_hi = (r_hi < M) ? g_dinv[r_hi] : 0.f;
#pragma unroll
        for (int j = 0; j < NT; j++) {
            int col = nbase + j * 8 + 2 * t;
            if (r_lo < M)
                *(float2*)&g_t[(size_t)r_lo * DOUT + col] =
                    make_float2(s_lo * acc[i][j][0], s_lo * acc[i][j][1]);
            if (r_hi < M)
                *(float2*)&g_t[(size_t)r_hi * DOUT + col] =
                    make_float2(s_hi * acc[i][j][2], s_hi * acc[i][j][3]);
        }
    }
}

// ================= Aggregation (warp per node), fused epilogue =================
template<int DOUT, int MODE>
__global__ void k_agg(const float* __restrict__ bias, float* __restrict__ out, int n) {
    int w    = (blockIdx.x * blockDim.x + threadIdx.x) >> 5;
    int lane = threadIdx.x & 31;
    if (w >= n) return;
    constexpr int VF = DOUT / 32;

    float acc[VF];
    {
        const float* p = g_t + (size_t)w * DOUT + lane * VF;
        if (VF == 4) { float4 v = *(const float4*)p; acc[0]=v.x; acc[1]=v.y; acc[2]=v.z; acc[3]=v.w; }
        else         { float2 v = *(const float2*)p; acc[0]=v.x; acc[1]=v.y; }
    }

    int beg = g_rowptr[w], end = g_rowptr[w + 1];
    for (int jb = beg; jb < end; jb += 32) {
        int myj = jb + lane;
        int ms  = (myj < end) ? g_csr_src[myj] : 0;
        int cnt = min(32, end - jb);
        int k = 0;
        for (; k + 4 <= cnt; k += 4) {
            int s0 = __shfl_sync(0xffffffffu, ms, k);
            int s1 = __shfl_sync(0xffffffffu, ms, k + 1);
            int s2 = __shfl_sync(0xffffffffu, ms, k + 2);
            int s3 = __shfl_sync(0xffffffffu, ms, k + 3);
            if (VF == 4) {
                float4 v0 = *(const float4*)(g_t + (size_t)s0 * DOUT + lane * 4);
                float4 v1 = *(const float4*)(g_t + (size_t)s1 * DOUT + lane * 4);
                float4 v2 = *(const float4*)(g_t + (size_t)s2 * DOUT + lane * 4);
                float4 v3 = *(const float4*)(g_t + (size_t)s3 * DOUT + lane * 4);
                acc[0] += (v0.x + v1.x) + (v2.x + v3.x);
                acc[1] += (v0.y + v1.y) + (v2.y + v3.y);
                acc[2] += (v0.z + v1.z) + (v2.z + v3.z);
                acc[3] += (v0.w + v1.w) + (v2.w + v3.w);
            } else {
                float2 v0 = *(const float2*)(g_t + (size_t)s0 * DOUT + lane * 2);
                float2 v1 = *(const float2*)(g_t + (size_t)s1 * DOUT + lane * 2);
                float2 v2 = *(const float2*)(g_t + (size_t)s2 * DOUT + lane * 2);
                float2 v3 = *(const float2*)(g_t + (size_t)s3 * DOUT + lane * 2);
                acc[0] += (v0.x + v1.x) + (v2.x + v3.x);
                acc[1] += (v0.y + v1.y) + (v2.y + v3.y);
            }
        }
        for (; k < cnt; k++) {
            int s = __shfl_sync(0xffffffffu, ms, k);
            if (VF == 4) {
                float4 v = *(const float4*)(g_t + (size_t)s * DOUT + lane * 4);
                acc[0] += v.x; acc[1] += v.y; acc[2] += v.z; acc[3] += v.w;
            } else {
                float2 v = *(const float2*)(g_t + (size_t)s * DOUT + lane * 2);
                acc[0] += v.x; acc[1] += v.y;
            }
        }
    }

    float di = g_dinv[w];
    if (MODE == 0) {
        float4 bb = ((const float4*)bias)[lane];
        float4 r;
        r.x = fmaxf(fmaf(di, acc[0], bb.x), 0.f);
        r.y = fmaxf(fmaf(di, acc[1], bb.y), 0.f);
        r.z = fmaxf(fmaf(di, acc[2], bb.z), 0.f);
        r.w = fmaxf(fmaf(di, acc[3], bb.w), 0.f);
        *(float4*)(g_h + (size_t)w * DOUT + lane * 4) = r;
    } else {
        float2 bb = ((const float2*)bias)[lane];
        float vx = fmaf(di, acc[0], bb.x);
        float vy = fmaf(di, acc[1], bb.y);
        float m = fmaxf(vx, vy);
#pragma unroll
        for (int o = 16; o; o >>= 1) m = fmaxf(m, __shfl_xor_sync(0xffffffffu, m, o));
        float sum = expf(vx - m) + expf(vy - m);
#pragma unroll
        for (int o = 16; o; o >>= 1) sum += __shfl_xor_sync(0xffffffffu, sum, o);
        float lse = m + logf(sum);
        *(float2*)(out + (size_t)w * 64 + lane * 2) = make_float2(vx - lse, vy - lse);
    }
}

// ================= launch =================
extern "C" void kernel_launch(void* const* d_in, const int* in_sizes, int n_in,
                              void* d_out, int out_size) {
    const float* x   = (const float*)d_in[0];
    const int*   ei  = (const int*)d_in[1];     // int32 (JAX x64 disabled)
    const float* W1  = (const float*)d_in[2];
    const float* b1  = (const float*)d_in[3];
    const float* W2  = (const float*)d_in[4];
    const float* b2  = (const float*)d_in[5];
    const float* W3  = (const float*)d_in[6];
    const float* b3  = (const float*)d_in[7];
    float* out = (float*)d_out;

    int n = in_sizes[0] / FIN;
    int e = in_sizes[1] / 2;
    const int* srcp = ei;
    const int* dstp = ei + e;

    const int smem128 = (128 * (FIN + 4) + 128 * (HH   + 8)) * sizeof(float); // ~134 KB
    const int smem64  = (128 * (FIN + 4) + 128 * (OUTC + 8)) * sizeof(float); // ~102 KB
    cudaFuncSetAttribute(k_gemm<HH>,   cudaFuncAttributeMaxDynamicSharedMemorySize, smem128);
    cudaFuncSetAttribute(k_gemm<OUTC>, cudaFuncAttributeMaxDynamicSharedMemorySize, smem64);

    int nb_scan = (n + 1023) >> 10;
    int gemm_blocks = (n + 127) / 128;
    int agg_blocks  = (int)(((long long)n * 32 + 255) / 256);

    // CSR build + dinv. Order chosen so launch #4 (ncu sample) = k_gemm layer 1.
    k_zero <<<(n + 255) / 256, 256>>>(n);                  // 1
    k_count<<<(e + 255) / 256, 256>>>(dstp, e);            // 2
    k_scan1<<<nb_scan, 1024>>>(n);                         // 3
    k_gemm<HH><<<gemm_blocks, 512, smem128>>>(x, W1, n, 0);// 4  <-- profiled
    k_scan2<<<1, 128>>>(nb_scan, n);                       // 5
    k_scan3<<<(n + 255) / 256, 256>>>(n);                  // 6
    k_fill <<<(e + 255) / 256, 256>>>(srcp, dstp, e);      // 7

    // layer 1 aggregate
    k_agg<HH, 0><<<agg_blocks, 256>>>(b1, nullptr, n);
    // layer 2
    k_gemm<HH><<<gemm_blocks, 512, smem128>>>(x, W2, n, 1);
    k_agg<HH, 0><<<agg_blocks, 256>>>(b2, nullptr, n);
    // layer 3
    k_gemm<OUTC><<<gemm_blocks, 512, smem64>>>(x, W3, n, 1);
    k_agg<OUTC, 1><<<agg_blocks, 256>>>(b3, out, n);
}

// round 8
// speedup vs baseline: 2.4896x; 1.0611x over previous
#include <cuda_runtime.h>
#include <cstdint>

#define NN   100000
#define EE   1600000
#define FIN  128
#define HH   128
#define OUTC 64

// ---------------- scratch (no allocation allowed) ----------------
__device__ __align__(16) int   g_cnt[NN];
__device__ __align__(16) int   g_rowptr[NN + 1];
__device__ __align__(16) int   g_cursor[NN];
__device__ __align__(16) int   g_bsum[256];
__device__ __align__(16) float g_dinv[NN];
__device__ __align__(16) int   g_csr_src[EE];
__device__ __align__(16) float g_t[(size_t)NN * HH];   // GEMM output (pre-scaled by dinv)
__device__ __align__(16) float g_h[(size_t)NN * HH];   // layer activation

// ================= CSR construction =================
__global__ void k_zero(int n) {
    int i = blockIdx.x * blockDim.x + threadIdx.x;
    if (i < n) g_cnt[i] = 0;
}
__global__ void k_count(const int* __restrict__ dst, int e) {
    int i = blockIdx.x * blockDim.x + threadIdx.x;
    if (i < e) atomicAdd(&g_cnt[dst[i]], 1);
}
__global__ void k_scan1(int n) {
    __shared__ int sh[1024];
    int tid = threadIdx.x;
    int i = blockIdx.x * 1024 + tid;
    int v = (i < n) ? g_cnt[i] : 0;
    sh[tid] = v;
    __syncthreads();
#pragma unroll
    for (int off = 1; off < 1024; off <<= 1) {
        int t = (tid >= off) ? sh[tid - off] : 0;
        __syncthreads();
        sh[tid] += t;
        __syncthreads();
    }
    if (i < n) {
        g_rowptr[i] = sh[tid] - v;                 // exclusive, local
        g_dinv[i]   = rsqrtf(1.0f + (float)v);     // +1 self-loop
    }
    if (tid == 1023) g_bsum[blockIdx.x] = sh[1023];
}
__global__ void k_scan2(int nb, int n) {
    __shared__ int sh[128];
    int tid = threadIdx.x;
    int v = (tid < nb) ? g_bsum[tid] : 0;
    sh[tid] = v;
    __syncthreads();
#pragma unroll
    for (int off = 1; off < 128; off <<= 1) {
        int t = (tid >= off) ? sh[tid - off] : 0;
        __syncthreads();
        sh[tid] += t;
        __syncthreads();
    }
    if (tid < nb) g_bsum[tid] = sh[tid] - v;
    if (tid == 127) g_rowptr[n] = sh[127];
}
__global__ void k_scan3(int n) {
    int i = blockIdx.x * blockDim.x + threadIdx.x;
    if (i >= n) return;
    int v = g_rowptr[i] + g_bsum[i >> 10];
    g_rowptr[i] = v;
    g_cursor[i] = v;
}
__global__ void k_fill(const int* __restrict__ src, const int* __restrict__ dst, int e) {
    int i = blockIdx.x * blockDim.x + threadIdx.x;
    if (i >= e) return;
    int d = dst[i];
    int pos = atomicAdd(&g_cursor[d], 1);
    g_csr_src[pos] = src[i];
}

// ================= TF32 helpers =================
__device__ __forceinline__ void split_tf32(float v, float& hi, float& lo) {
    hi = __uint_as_float(__float_as_uint(v) & 0xFFFFE000u);  // exact tf32 truncation
    lo = v - hi;                                             // exact residual
}
__device__ __forceinline__ void mma_tf32(float c[4], const float a[4], const float b[2]) {
    asm volatile(
        "mma.sync.aligned.m16n8k8.row.col.f32.tf32.tf32.f32 "
        "{%0,%1,%2,%3}, {%4,%5,%6,%7}, {%8,%9}, {%0,%1,%2,%3};"
        : "+f"(c[0]), "+f"(c[1]), "+f"(c[2]), "+f"(c[3])
        : "r"(__float_as_uint(a[0])), "r"(__float_as_uint(a[1])),
          "r"(__float_as_uint(a[2])), "r"(__float_as_uint(a[3])),
          "r"(__float_as_uint(b[0])), "r"(__float_as_uint(b[1])));
}

// ================= GEMM: g_t[M,DOUT] = dinv[row] * (A[M,128] @ W[128,DOUT]) =================
// 256 threads (8 warps, 2m x 4n). CTA tile 64 x DOUT -> 2-3 CTAs/SM for overlap.
// Per warp: 32 rows (2 m16 tiles) x DOUT/4 cols (NT = DOUT/32 n8-tiles).
template<int DOUT>
__global__ __launch_bounds__(256, 2)
void k_gemm(const float* __restrict__ Ax, const float* __restrict__ W,
            int M, int from_h) {
    constexpr int DIN = 128;
    constexpr int AST = DIN + 4;      // A smem stride: frag banks conflict-free
    constexpr int WST = DOUT + 8;     // W smem stride: frag banks conflict-free
    constexpr int NT  = DOUT / 32;    // n8-tiles per warp (4 or 2)

    extern __shared__ float sm[];
    float* As = sm;                   // [64][AST]
    float* Ws = sm + 64 * AST;        // [128][WST]  row=k, col=n

    const float* A = from_h ? g_h : Ax;
    int tid  = threadIdx.x;
    int row0 = blockIdx.x * 64;

    // stage W
    for (int i = tid; i < DIN * (DOUT / 4); i += 256) {
        int r  = i / (DOUT / 4);
        int c4 = i % (DOUT / 4);
        *(float4*)(Ws + r * WST + c4 * 4) = ((const float4*)W)[i];
    }
    // stage A (zero-fill OOB rows)
    for (int i = tid; i < 64 * 32; i += 256) {
        int r  = i >> 5;
        int c4 = i & 31;
        int gr = row0 + r;
        float4 v = make_float4(0.f, 0.f, 0.f, 0.f);
        if (gr < M) v = ((const float4*)A)[(size_t)gr * 32 + c4];
        *(float4*)(As + r * AST + c4 * 4) = v;
    }
    __syncthreads();

    int warp = tid >> 5, lane = tid & 31;
    int wm = warp & 1;                 // 0..1
    int wn = warp >> 1;                // 0..3
    int g  = lane >> 2;                // group id 0..7
    int t  = lane & 3;                 // thread in group 0..3
    int mbase = wm * 32;
    int nbase = wn * (DOUT / 4);

    float acc[2][NT][4];
#pragma unroll
    for (int i = 0; i < 2; i++)
#pragma unroll
        for (int j = 0; j < NT; j++)
#pragma unroll
            for (int q = 0; q < 4; q++) acc[i][j][q] = 0.f;

#pragma unroll 2
    for (int kk = 0; kk < DIN; kk += 8) {
        float ahi[2][4], alo[2][4];
#pragma unroll
        for (int i = 0; i < 2; i++) {
            const float* ap = As + (mbase + i * 16 + g) * AST + kk + t;
            float a0 = ap[0];
            float a1 = ap[8 * AST];
            float a2 = ap[4];
            float a3 = ap[8 * AST + 4];
            split_tf32(a0, ahi[i][0], alo[i][0]);
            split_tf32(a1, ahi[i][1], alo[i][1]);
            split_tf32(a2, ahi[i][2], alo[i][2]);
            split_tf32(a3, ahi[i][3], alo[i][3]);
        }
        float bhi[NT][2], blo[NT][2];
#pragma unroll
        for (int j = 0; j < NT; j++) {
            const float* bp = Ws + (kk + t) * WST + nbase + j * 8 + g;
            float b0 = bp[0];
            float b1 = bp[4 * WST];
            split_tf32(b0, bhi[j][0], blo[j][0]);
            split_tf32(b1, bhi[j][1], blo[j][1]);
        }
#pragma unroll
        for (int i = 0; i < 2; i++)
#pragma unroll
            for (int j = 0; j < NT; j++) {
                mma_tf32(acc[i][j], ahi[i], bhi[j]);
                mma_tf32(acc[i][j], ahi[i], blo[j]);
                mma_tf32(acc[i][j], alo[i], bhi[j]);
            }
    }

    // epilogue: scale by dinv, store float2 pairs
#pragma unroll
    for (int i = 0; i < 2; i++) {
        int r_lo = row0 + mbase + i * 16 + g;
        int r_hi = r_lo + 8;
        float s_lo = (r_lo < M) ? g_dinv[r_lo] : 0.f;
        float s_hi = (r_hi < M) ? g_dinv[r_hi] : 0.f;
#pragma unroll
        for (int j = 0; j < NT; j++) {
            int col = nbase + j * 8 + 2 * t;
            if (r_lo < M)
                *(float2*)&g_t[(size_t)r_lo * DOUT + col] =
                    make_float2(s_lo * acc[i][j][0], s_lo * acc[i][j][1]);
            if (r_hi < M)
                *(float2*)&g_t[(size_t)r_hi * DOUT + col] =
                    make_float2(s_hi * acc[i][j][2], s_hi * acc[i][j][3]);
        }
    }
}

// ================= Aggregation (warp per node), fused epilogue =================
template<int DOUT, int MODE>
__global__ void k_agg(const float* __restrict__ bias, float* __restrict__ out, int n) {
    int w    = (blockIdx.x * blockDim.x + threadIdx.x) >> 5;
    int lane = threadIdx.x & 31;
    if (w >= n) return;
    constexpr int VF = DOUT / 32;

    float acc[VF];
    {
        const float* p = g_t + (size_t)w * DOUT + lane * VF;
        if (VF == 4) { float4 v = *(const float4*)p; acc[0]=v.x; acc[1]=v.y; acc[2]=v.z; acc[3]=v.w; }
        else         { float2 v = *(const float2*)p; acc[0]=v.x; acc[1]=v.y; }
    }

    int beg = g_rowptr[w], end = g_rowptr[w + 1];
    for (int jb = beg; jb < end; jb += 32) {
        int myj = jb + lane;
        int ms  = (myj < end) ? g_csr_src[myj] : 0;
        int cnt = min(32, end - jb);
        int k = 0;
        for (; k + 4 <= cnt; k += 4) {
            int s0 = __shfl_sync(0xffffffffu, ms, k);
            int s1 = __shfl_sync(0xffffffffu, ms, k + 1);
            int s2 = __shfl_sync(0xffffffffu, ms, k + 2);
            int s3 = __shfl_sync(0xffffffffu, ms, k + 3);
            if (VF == 4) {
                float4 v0 = *(const float4*)(g_t + (size_t)s0 * DOUT + lane * 4);
                float4 v1 = *(const float4*)(g_t + (size_t)s1 * DOUT + lane * 4);
                float4 v2 = *(const float4*)(g_t + (size_t)s2 * DOUT + lane * 4);
                float4 v3 = *(const float4*)(g_t + (size_t)s3 * DOUT + lane * 4);
                acc[0] += (v0.x + v1.x) + (v2.x + v3.x);
                acc[1] += (v0.y + v1.y) + (v2.y + v3.y);
                acc[2] += (v0.z + v1.z) + (v2.z + v3.z);
                acc[3] += (v0.w + v1.w) + (v2.w + v3.w);
            } else {
                float2 v0 = *(const float2*)(g_t + (size_t)s0 * DOUT + lane * 2);
                float2 v1 = *(const float2*)(g_t + (size_t)s1 * DOUT + lane * 2);
                float2 v2 = *(const float2*)(g_t + (size_t)s2 * DOUT + lane * 2);
                float2 v3 = *(const float2*)(g_t + (size_t)s3 * DOUT + lane * 2);
                acc[0] += (v0.x + v1.x) + (v2.x + v3.x);
                acc[1] += (v0.y + v1.y) + (v2.y + v3.y);
            }
        }
        for (; k < cnt; k++) {
            int s = __shfl_sync(0xffffffffu, ms, k);
            if (VF == 4) {
                float4 v = *(const float4*)(g_t + (size_t)s * DOUT + lane * 4);
                acc[0] += v.x; acc[1] += v.y; acc[2] += v.z; acc[3] += v.w;
            } else {
                float2 v = *(const float2*)(g_t + (size_t)s * DOUT + lane * 2);
                acc[0] += v.x; acc[1] += v.y;
            }
        }
    }

    float di = g_dinv[w];
    if (MODE == 0) {
        float4 bb = ((const float4*)bias)[lane];
        float4 r;
        r.x = fmaxf(fmaf(di, acc[0], bb.x), 0.f);
        r.y = fmaxf(fmaf(di, acc[1], bb.y), 0.f);
        r.z = fmaxf(fmaf(di, acc[2], bb.z), 0.f);
        r.w = fmaxf(fmaf(di, acc[3], bb.w), 0.f);
        *(float4*)(g_h + (size_t)w * DOUT + lane * 4) = r;
    } else {
        float2 bb = ((const float2*)bias)[lane];
        float vx = fmaf(di, acc[0], bb.x);
        float vy = fmaf(di, acc[1], bb.y);
        float m = fmaxf(vx, vy);
#pragma unroll
        for (int o = 16; o; o >>= 1) m = fmaxf(m, __shfl_xor_sync(0xffffffffu, m, o));
        float sum = expf(vx - m) + expf(vy - m);
#pragma unroll
        for (int o = 16; o; o >>= 1) sum += __shfl_xor_sync(0xffffffffu, sum, o);
        float lse = m + logf(sum);
        *(float2*)(out + (size_t)w * 64 + lane * 2) = make_float2(vx - lse, vy - lse);
    }
}

// ================= launch =================
extern "C" void kernel_launch(void* const* d_in, const int* in_sizes, int n_in,
                              void* d_out, int out_size) {
    const float* x   = (const float*)d_in[0];
    const int*   ei  = (const int*)d_in[1];     // int32 (JAX x64 disabled)
    const float* W1  = (const float*)d_in[2];
    const float* b1  = (const float*)d_in[3];
    const float* W2  = (const float*)d_in[4];
    const float* b2  = (const float*)d_in[5];
    const float* W3  = (const float*)d_in[6];
    const float* b3  = (const float*)d_in[7];
    float* out = (float*)d_out;

    int n = in_sizes[0] / FIN;
    int e = in_sizes[1] / 2;
    const int* srcp = ei;
    const int* dstp = ei + e;

    const int smem128 = (64 * (FIN + 4) + 128 * (HH   + 8)) * sizeof(float); // ~101 KB -> 2 CTA/SM
    const int smem64  = (64 * (FIN + 4) + 128 * (OUTC + 8)) * sizeof(float); // ~69 KB  -> 3 CTA/SM
    cudaFuncSetAttribute(k_gemm<HH>,   cudaFuncAttributeMaxDynamicSharedMemorySize, smem128);
    cudaFuncSetAttribute(k_gemm<OUTC>, cudaFuncAttributeMaxDynamicSharedMemorySize, smem64);

    int nb_scan = (n + 1023) >> 10;
    int gemm_blocks = (n + 63) / 64;
    int agg_blocks  = (int)(((long long)n * 32 + 255) / 256);

    // CSR build + dinv. Order chosen so launch #4 (ncu sample) = k_gemm layer 1.
    k_zero <<<(n + 255) / 256, 256>>>(n);                  // 1
    k_count<<<(e + 255) / 256, 256>>>(dstp, e);            // 2
    k_scan1<<<nb_scan, 1024>>>(n);                         // 3
    k_gemm<HH><<<gemm_blocks, 256, smem128>>>(x, W1, n, 0);// 4  <-- profiled
    k_scan2<<<1, 128>>>(nb_scan, n);                       // 5
    k_scan3<<<(n + 255) / 256, 256>>>(n);                  // 6
    k_fill <<<(e + 255) / 256, 256>>>(srcp, dstp, e);      // 7

    // layer 1 aggregate
    k_agg<HH, 0><<<agg_blocks, 256>>>(b1, nullptr, n);
    // layer 2
    k_gemm<HH><<<gemm_blocks, 256, smem128>>>(x, W2, n, 1);
    k_agg<HH, 0><<<agg_blocks, 256>>>(b2, nullptr, n);
    // layer 3
    k_gemm<OUTC><<<gemm_blocks, 256, smem64>>>(x, W3, n, 1);
    k_agg<OUTC, 1><<<agg_blocks, 256>>>(b3, out, n);
}